// round 1
// baseline (speedup 1.0000x reference)
#include <cuda_runtime.h>

// Problem constants: B=256 (batch), T=64 (channels), S=16 (grid), U=4 (upscale)
// P = S*S = 256 pixels, O = U*U*T = 1024 outputs per pixel.
//
// Plan:
//  kernel 1: transpose x (B,T,S,S) -> g_xT[p][b][t] with tf32 rounding (coalesced both sides via smem tile)
//  kernel 2: per-pixel GEMM C[128x128] tiles via mma.sync.m16n8k8 tf32, K=64 single-shot,
//            epilogue adds bias and scatters into pixel-shuffle layout (B, T, 64, 64).

__device__ float g_xT[256 * 256 * 64];  // [p][b][t], tf32-rounded, 16.7 MB scratch

__device__ __forceinline__ unsigned int f2tf32(float f) {
    unsigned int r;
    asm("cvt.rna.tf32.f32 %0, %1;" : "=r"(r) : "f"(f));
    return r;
}

// ---------------------------------------------------------------------------
// Transpose: x[b*16384 + t*256 + p] -> g_xT[p*16384 + b*64 + t]
// grid (8 p-tiles, 2 t-tiles, 256 b), block (32, 8)
// ---------------------------------------------------------------------------
__global__ void transpose_kernel(const float* __restrict__ x) {
    __shared__ float tile[32][33];
    int p0 = blockIdx.x * 32;
    int t0 = blockIdx.y * 32;
    int b  = blockIdx.z;
    int tx = threadIdx.x, ty = threadIdx.y;

    const float* src = x + (size_t)b * 16384 + (size_t)t0 * 256 + p0;
#pragma unroll
    for (int k = 0; k < 4; k++) {
        int t = ty + k * 8;
        float v = src[t * 256 + tx];          // coalesced over p (=tx)
        tile[t][tx] = __uint_as_float(f2tf32(v));
    }
    __syncthreads();
    float* dst = g_xT + (size_t)p0 * 16384 + (size_t)b * 64 + t0;
#pragma unroll
    for (int k = 0; k < 4; k++) {
        int pl = ty + k * 8;
        dst[(size_t)pl * 16384 + tx] = tile[tx][pl];  // coalesced over t (=tx)
    }
}

// ---------------------------------------------------------------------------
// GEMM: per pixel p, C[b, o] = sum_t xT[p,b,t] * W[p,o,t] + bias[p,o]
// Block tile: 128 (b) x 128 (o), K = 64 full. 256 threads = 8 warps (2x4),
// warp tile 64x32, m16n8k8 tf32 fragments.
// smem row stride 68 floats (272 B): 16B-aligned rows, conflict-free frag loads.
// ---------------------------------------------------------------------------
#define SROW 68
#define SMEM_BYTES (2 * 128 * SROW * 4)

__global__ __launch_bounds__(256) void gemm_kernel(const float* __restrict__ Wg_all,
                                                   const float* __restrict__ bias,
                                                   float* __restrict__ out) {
    extern __shared__ float smem[];
    float* As = smem;               // [128][SROW]  (b-rows, t-cols)
    float* Bs = smem + 128 * SROW;  // [128][SROW]  (o-rows, t-cols)
    __shared__ float bias_s[128];

    int p  = blockIdx.z;   // pixel
    int bm = blockIdx.y;   // 0..1  (batch tile)
    int bn = blockIdx.x;   // 0..7  (output tile)
    int tid  = threadIdx.x;
    int lane = tid & 31, warp = tid >> 5;
    int wm = warp >> 2, wn = warp & 3;

    const float* Ag = g_xT + ((size_t)p << 14) + (size_t)(bm * 128) * 64;
    const float* Wg = Wg_all + ((size_t)p << 16) + (size_t)(bn * 128) * 64;

    // Stage A (already tf32-rounded) and B (round here) into smem, float4 loads.
#pragma unroll
    for (int i2 = 0; i2 < 8; i2++) {
        int idx = tid + i2 * 256;
        int r = idx >> 4;
        int c = (idx & 15) << 2;
        float4 av = *(const float4*)(Ag + r * 64 + c);
        *(float4*)(As + r * SROW + c) = av;
        float4 wv = *(const float4*)(Wg + r * 64 + c);
        uint4 u = make_uint4(f2tf32(wv.x), f2tf32(wv.y), f2tf32(wv.z), f2tf32(wv.w));
        *(uint4*)(Bs + r * SROW + c) = u;
    }
    if (tid < 128) bias_s[tid] = bias[(size_t)p * 1024 + bn * 128 + tid];
    __syncthreads();

    float acc[4][4][4];
#pragma unroll
    for (int mi = 0; mi < 4; mi++)
#pragma unroll
        for (int ni = 0; ni < 4; ni++)
#pragma unroll
            for (int q = 0; q < 4; q++) acc[mi][ni][q] = 0.f;

    int qr = lane >> 2;   // group id (0..7)
    int qc = lane & 3;    // thread-in-group (0..3)

#pragma unroll
    for (int k0 = 0; k0 < 64; k0 += 8) {
        unsigned int a[4][4], b[4][2];
#pragma unroll
        for (int mi = 0; mi < 4; mi++) {
            const float* ab = As + (wm * 64 + mi * 16 + qr) * SROW + k0 + qc;
            a[mi][0] = __float_as_uint(ab[0]);
            a[mi][1] = __float_as_uint(ab[8 * SROW]);
            a[mi][2] = __float_as_uint(ab[4]);
            a[mi][3] = __float_as_uint(ab[8 * SROW + 4]);
        }
#pragma unroll
        for (int ni = 0; ni < 4; ni++) {
            const float* bb = Bs + (wn * 32 + ni * 8 + qr) * SROW + k0 + qc;
            b[ni][0] = __float_as_uint(bb[0]);
            b[ni][1] = __float_as_uint(bb[4]);
        }
#pragma unroll
        for (int mi = 0; mi < 4; mi++)
#pragma unroll
            for (int ni = 0; ni < 4; ni++) {
                asm("mma.sync.aligned.m16n8k8.row.col.f32.tf32.tf32.f32 "
                    "{%0,%1,%2,%3}, {%4,%5,%6,%7}, {%8,%9}, {%0,%1,%2,%3};"
                    : "+f"(acc[mi][ni][0]), "+f"(acc[mi][ni][1]),
                      "+f"(acc[mi][ni][2]), "+f"(acc[mi][ni][3])
                    : "r"(a[mi][0]), "r"(a[mi][1]), "r"(a[mi][2]), "r"(a[mi][3]),
                      "r"(b[ni][0]), "r"(b[ni][1]));
            }
    }

    // Epilogue: o = t*16 + ui*4 + uj ; out[b][t][i*4+ui][j*4+uj], out is (256,64,64,64)
    int i4 = (p >> 4) << 2;   // i*4
    int j4 = (p & 15) << 2;   // j*4
#pragma unroll
    for (int ni = 0; ni < 4; ni++) {
        int o_loc = wn * 32 + ni * 8 + 2 * qc;       // even -> (uj, uj+1) pair contiguous
        int o = bn * 128 + o_loc;
        int t  = o >> 4;
        int ui = (o >> 2) & 3;
        int uj = o & 3;
        int coloff = t * 4096 + (i4 + ui) * 64 + j4 + uj;
        float b0 = bias_s[o_loc];
        float b1 = bias_s[o_loc + 1];
#pragma unroll
        for (int mi = 0; mi < 4; mi++) {
            int row = bm * 128 + wm * 64 + mi * 16 + qr;
            float2 v0 = make_float2(acc[mi][ni][0] + b0, acc[mi][ni][1] + b1);
            float2 v1 = make_float2(acc[mi][ni][2] + b0, acc[mi][ni][3] + b1);
            *(float2*)(out + (size_t)row * 262144 + coloff) = v0;
            *(float2*)(out + (size_t)(row + 8) * 262144 + coloff) = v1;
        }
    }
}

extern "C" void kernel_launch(void* const* d_in, const int* in_sizes, int n_in,
                              void* d_out, int out_size) {
    const float* x  = (const float*)d_in[0];   // (256, 64, 16, 16)
    const float* W  = (const float*)d_in[1];   // (256, 1024, 64)
    const float* b  = (const float*)d_in[2];   // (256, 1024)
    float* out = (float*)d_out;                // (256, 64, 64, 64)

    (void)in_sizes; (void)n_in; (void)out_size;

    cudaFuncSetAttribute(gemm_kernel, cudaFuncAttributeMaxDynamicSharedMemorySize, SMEM_BYTES);

    transpose_kernel<<<dim3(8, 2, 256), dim3(32, 8)>>>(x);
    gemm_kernel<<<dim3(8, 2, 256), 256, SMEM_BYTES>>>(W, b, out);
}

// round 2
// speedup vs baseline: 1.0546x; 1.0546x over previous
#include <cuda_runtime.h>

// B=256 (batch), T=64 (K), S=16, U=4  ->  P=256 pixels, O=1024 outputs/pixel.
// kernel 1: transpose x (B,T,S,S) -> g_xT[p][b][t], tf32-rounded.
// kernel 2: CTA = (pixel, N-half). A = full 256x64 batch tile in smem (read once),
//           W streamed in 4 chunks of 128x64 via cp.async double buffer (read once),
//           tf32 m16n8k8 mma, per-chunk epilogue scatters into pixel-shuffle layout.

__device__ float g_xT[256 * 256 * 64];  // [p][b][t]

__device__ __forceinline__ unsigned int f2tf32(float f) {
    unsigned int r;
    asm("cvt.rna.tf32.f32 %0, %1;" : "=r"(r) : "f"(f));
    return r;
}

__device__ __forceinline__ void cp16(float* smem_dst, const float* gmem_src) {
    unsigned s = (unsigned)__cvta_generic_to_shared(smem_dst);
    asm volatile("cp.async.cg.shared.global [%0], [%1], 16;\n" :: "r"(s), "l"(gmem_src));
}

// ---------------------------------------------------------------------------
// Transpose: x[b*16384 + t*256 + p] -> g_xT[p*16384 + b*64 + t]
// ---------------------------------------------------------------------------
__global__ void transpose_kernel(const float* __restrict__ x) {
    __shared__ float tile[32][33];
    int p0 = blockIdx.x * 32;
    int t0 = blockIdx.y * 32;
    int b  = blockIdx.z;
    int tx = threadIdx.x, ty = threadIdx.y;

    const float* src = x + (size_t)b * 16384 + (size_t)t0 * 256 + p0;
#pragma unroll
    for (int k = 0; k < 4; k++) {
        int t = ty + k * 8;
        tile[t][tx] = __uint_as_float(f2tf32(src[t * 256 + tx]));
    }
    __syncthreads();
    float* dst = g_xT + (size_t)p0 * 16384 + (size_t)b * 64 + t0;
#pragma unroll
    for (int k = 0; k < 4; k++) {
        int pl = ty + k * 8;
        dst[(size_t)pl * 16384 + tx] = tile[tx][pl];
    }
}

// ---------------------------------------------------------------------------
// GEMM: CTA = (half h, pixel p). M=256 (batch), N=512 (half), K=64.
// 512 threads = 16 warps (4m x 4n), warp tile 64x32, m16n8k8 tf32.
// ---------------------------------------------------------------------------
#define SROW 68
#define AS_FLOATS (256 * SROW)
#define WS_FLOATS (128 * SROW)
#define SMEM_BYTES ((AS_FLOATS + 2 * WS_FLOATS + 512) * 4)

__global__ __launch_bounds__(512, 1) void gemm_kernel(const float* __restrict__ Wg_all,
                                                      const float* __restrict__ bias,
                                                      float* __restrict__ out) {
    extern __shared__ float smem[];
    float* As     = smem;                            // [256][SROW]
    float* Ws     = smem + AS_FLOATS;                // [2][128][SROW]
    float* bias_s = smem + AS_FLOATS + 2 * WS_FLOATS; // [512]

    int h = blockIdx.x;   // 0..1   N-half
    int p = blockIdx.y;   // pixel
    int tid  = threadIdx.x;
    int lane = tid & 31, warp = tid >> 5;
    int wm = warp >> 2, wn = warp & 3;
    int qr = lane >> 2, qc = lane & 3;

    const float* Ag = g_xT + ((size_t)p << 14);
    const float* Wg = Wg_all + ((size_t)p << 16) + (size_t)(h * 512) * 64;

    // A tile: 256x64 = 4096 16B slots, 8 per thread
#pragma unroll
    for (int i = 0; i < 8; i++) {
        int idx = tid + i * 512;
        int r = idx >> 4, c = (idx & 15) << 2;
        cp16(As + r * SROW + c, Ag + r * 64 + c);
    }
    asm volatile("cp.async.commit_group;\n" ::);
    // W chunk 0 -> buf 0
#pragma unroll
    for (int i = 0; i < 4; i++) {
        int idx = tid + i * 512;
        int r = idx >> 4, c = (idx & 15) << 2;
        cp16(Ws + r * SROW + c, Wg + r * 64 + c);
    }
    asm volatile("cp.async.commit_group;\n" ::);
    // W chunk 1 -> buf 1
#pragma unroll
    for (int i = 0; i < 4; i++) {
        int idx = tid + i * 512;
        int r = idx >> 4, c = (idx & 15) << 2;
        cp16(Ws + WS_FLOATS + r * SROW + c, Wg + 128 * 64 + r * 64 + c);
    }
    asm volatile("cp.async.commit_group;\n" ::);

    bias_s[tid] = bias[(size_t)p * 1024 + h * 512 + tid];

    int i4 = (p >> 4) << 2;   // i*4
    int j4 = (p & 15) << 2;   // j*4

    float acc[4][4][4];
#pragma unroll
    for (int mi = 0; mi < 4; mi++)
#pragma unroll
        for (int ni = 0; ni < 4; ni++)
#pragma unroll
            for (int q = 0; q < 4; q++) acc[mi][ni][q] = 0.f;

#pragma unroll
    for (int nc = 0; nc < 4; nc++) {
        if (nc < 3) asm volatile("cp.async.wait_group 1;\n" ::);
        else        asm volatile("cp.async.wait_group 0;\n" ::);
        __syncthreads();

        const float* Bsb = Ws + (nc & 1) * WS_FLOATS;

#pragma unroll
        for (int k0 = 0; k0 < 64; k0 += 8) {
            unsigned int a[4][4], b[4][2];
#pragma unroll
            for (int mi = 0; mi < 4; mi++) {
                const float* ab = As + (wm * 64 + mi * 16 + qr) * SROW + k0 + qc;
                a[mi][0] = __float_as_uint(ab[0]);
                a[mi][1] = __float_as_uint(ab[8 * SROW]);
                a[mi][2] = __float_as_uint(ab[4]);
                a[mi][3] = __float_as_uint(ab[8 * SROW + 4]);
            }
#pragma unroll
            for (int ni = 0; ni < 4; ni++) {
                const float* bb = Bsb + (wn * 32 + ni * 8 + qr) * SROW + k0 + qc;
                b[ni][0] = f2tf32(bb[0]);
                b[ni][1] = f2tf32(bb[4]);
            }
#pragma unroll
            for (int mi = 0; mi < 4; mi++)
#pragma unroll
                for (int ni = 0; ni < 4; ni++) {
                    asm("mma.sync.aligned.m16n8k8.row.col.f32.tf32.tf32.f32 "
                        "{%0,%1,%2,%3}, {%4,%5,%6,%7}, {%8,%9}, {%0,%1,%2,%3};"
                        : "+f"(acc[mi][ni][0]), "+f"(acc[mi][ni][1]),
                          "+f"(acc[mi][ni][2]), "+f"(acc[mi][ni][3])
                        : "r"(a[mi][0]), "r"(a[mi][1]), "r"(a[mi][2]), "r"(a[mi][3]),
                          "r"(b[ni][0]), "r"(b[ni][1]));
                }
        }

        // Epilogue for this chunk: o = h*512 + nc*128 + o_loc, viewed as (t, ui, uj)
#pragma unroll
        for (int ni = 0; ni < 4; ni++) {
            int o_loc = wn * 32 + ni * 8 + 2 * qc;
            int o = h * 512 + nc * 128 + o_loc;
            int t  = o >> 4;
            int ui = (o >> 2) & 3;
            int uj = o & 3;
            int coloff = t * 4096 + (i4 + ui) * 64 + j4 + uj;
            float b0 = bias_s[nc * 128 + o_loc];
            float b1 = bias_s[nc * 128 + o_loc + 1];
#pragma unroll
            for (int mi = 0; mi < 4; mi++) {
                int row = wm * 64 + mi * 16 + qr;
                *(float2*)(out + (size_t)row * 262144 + coloff) =
                    make_float2(acc[mi][ni][0] + b0, acc[mi][ni][1] + b1);
                *(float2*)(out + (size_t)(row + 8) * 262144 + coloff) =
                    make_float2(acc[mi][ni][2] + b0, acc[mi][ni][3] + b1);
                acc[mi][ni][0] = 0.f; acc[mi][ni][1] = 0.f;
                acc[mi][ni][2] = 0.f; acc[mi][ni][3] = 0.f;
            }
        }

        __syncthreads();   // all warps done reading Ws[nc&1] before refill

        if (nc < 2) {
            float* dst = Ws + (nc & 1) * WS_FLOATS;
            const float* src = Wg + (size_t)(nc + 2) * 128 * 64;
#pragma unroll
            for (int i = 0; i < 4; i++) {
                int idx = tid + i * 512;
                int r = idx >> 4, c = (idx & 15) << 2;
                cp16(dst + r * SROW + c, src + r * 64 + c);
            }
            asm volatile("cp.async.commit_group;\n" ::);
        }
    }
}

extern "C" void kernel_launch(void* const* d_in, const int* in_sizes, int n_in,
                              void* d_out, int out_size) {
    const float* x  = (const float*)d_in[0];   // (256, 64, 16, 16)
    const float* W  = (const float*)d_in[1];   // (256, 1024, 64)
    const float* b  = (const float*)d_in[2];   // (256, 1024)
    float* out = (float*)d_out;                // (256, 64, 64, 64)

    (void)in_sizes; (void)n_in; (void)out_size;

    cudaFuncSetAttribute(gemm_kernel, cudaFuncAttributeMaxDynamicSharedMemorySize, SMEM_BYTES);

    transpose_kernel<<<dim3(8, 2, 256), dim3(32, 8)>>>(x);
    gemm_kernel<<<dim3(2, 256), 512, SMEM_BYTES>>>(W, b, out);
}